// round 4
// baseline (speedup 1.0000x reference)
#include <cuda_runtime.h>
#include <cuda_bf16.h>
#include <math.h>
#include <stdint.h>

#define BB   2
#define SS   2048
#define DD   2048
#define HH   16
#define HD   128
#define FF   8192
#define MM   (BB*SS)          // 4096
#define QKVW (3*DD)           // 6144

// ---------------- fp32 scratch ----------------
__device__ float g_xn [MM*DD];
__device__ float g_qkv[MM*QKVW];
__device__ float g_att[MM*DD];
__device__ float g_h  [MM*DD];
__device__ float g_a1 [MM*FF];
__device__ float g_g  [MM*FF];

// ---------------- bf16 split scratch (tile-packed [rows/128][3K/64][128][64], SW128 swizzled)
__device__ __nv_bfloat16 g_xn3 [(size_t)MM*3*DD];
__device__ __nv_bfloat16 g_att3[(size_t)MM*3*DD];
__device__ __nv_bfloat16 g_h3  [(size_t)MM*3*DD];
__device__ __nv_bfloat16 g_gg3 [(size_t)MM*3*FF];
__device__ __nv_bfloat16 g_wqkv3[(size_t)QKVW*3*DD];
__device__ __nv_bfloat16 g_wout3[(size_t)DD*3*DD];
__device__ __nv_bfloat16 g_w13 [(size_t)FF*3*DD];
__device__ __nv_bfloat16 g_w33 [(size_t)FF*3*DD];
__device__ __nv_bfloat16 g_w23 [(size_t)DD*3*FF];

// ---------------- PTX helpers (sm_90 baseline features only) -----------------
__device__ __forceinline__ uint32_t smem_u32(const void* p) {
    uint32_t a;
    asm("{ .reg .u64 t; cvta.to.shared.u64 t, %1; cvt.u32.u64 %0, t; }" : "=r"(a) : "l"(p));
    return a;
}
__device__ __forceinline__ uint32_t elect_one() {
    uint32_t p;
    asm volatile("{ .reg .pred p; elect.sync _|p, 0xFFFFFFFF; selp.b32 %0,1,0,p; }" : "=r"(p));
    return p;
}
#define MBAR_INIT(a, c) \
    asm volatile("mbarrier.init.shared.b64 [%0], %1;" :: "r"(a), "r"(c) : "memory")
#define MBAR_EXPECT(a, b) \
    asm volatile("mbarrier.arrive.expect_tx.shared.b64 _, [%0], %1;" :: "r"(a), "r"(b) : "memory")
#define MBAR_ARRIVE(a) \
    asm volatile("mbarrier.arrive.shared.b64 _, [%0];" :: "r"(a) : "memory")
#define MBAR_WAIT(a, ph) do { uint32_t _m=(a), _p=(ph), _d;                                   \
    asm volatile("{ .reg .pred p; mbarrier.try_wait.parity.acquire.cta.shared::cta.b64 p, [%1], %2; selp.b32 %0,1,0,p; }" \
                 : "=r"(_d) : "r"(_m), "r"(_p) : "memory");                                   \
    if (!_d) {                                                                                \
      asm volatile("{ .reg .pred P1; WL%=: mbarrier.try_wait.parity.acquire.cta.shared::cta.b64 P1, [%0], %1, 0x989680; @P1 bra.uni WD%=; bra.uni WL%=; WD%=: }" \
                   :: "r"(_m), "r"(_p) : "memory"); } } while(0)
#define BULK_G2S(d, s, n, m) \
    asm volatile("cp.async.bulk.shared::cta.global.mbarrier::complete_tx::bytes [%0], [%1], %2, [%3];" \
                 :: "r"(d), "l"(s), "r"(n), "r"(m) : "memory")
#define LDSM_X4(r0, r1, r2, r3, a) \
    asm volatile("ldmatrix.sync.aligned.m8n8.x4.shared.b16 {%0,%1,%2,%3}, [%4];" \
                 : "=r"(r0), "=r"(r1), "=r"(r2), "=r"(r3) : "r"(a))
#define MMA16816(d, av, bv) \
    asm volatile("mma.sync.aligned.m16n8k16.row.col.f32.bf16.bf16.f32 " \
                 "{%0,%1,%2,%3}, {%4,%5,%6,%7}, {%8,%9}, {%0,%1,%2,%3};" \
                 : "+f"((d)[0]), "+f"((d)[1]), "+f"((d)[2]), "+f"((d)[3]) \
                 : "r"((av)[0]), "r"((av)[1]), "r"((av)[2]), "r"((av)[3]), \
                   "r"((bv)[0]), "r"((bv)[1]))

// ---------------- RMSNorm ----------------------------------------------------
__global__ __launch_bounds__(256) void rmsnorm_kernel(
    const float* __restrict__ x, const float* __restrict__ w, float* __restrict__ out)
{
    const int row = blockIdx.x;
    const float* xr = x + (size_t)row * DD;
    float ss = 0.f;
    for (int i = threadIdx.x; i < DD; i += 256) { float v = xr[i]; ss = fmaf(v, v, ss); }
    #pragma unroll
    for (int o = 16; o; o >>= 1) ss += __shfl_xor_sync(0xffffffffu, ss, o);
    __shared__ float sred[8];
    if ((threadIdx.x & 31) == 0) sred[threadIdx.x >> 5] = ss;
    __syncthreads();
    float tot = sred[0]+sred[1]+sred[2]+sred[3]+sred[4]+sred[5]+sred[6]+sred[7];
    float sc = rsqrtf(tot * (1.0f / DD) + 1e-5f);
    float* orow = out + (size_t)row * DD;
    for (int i = threadIdx.x; i < DD; i += 256) orow[i] = xr[i] * sc * w[i];
}

// ---------------- fp32 -> bf16 hi/lo split, tile-packed, pre-swizzled --------
// acts:    copies along K' are (hi, lo, hi) ; weights: (hi, hi, lo)
__global__ __launch_bounds__(256) void convert3(
    const float* __restrict__ src, __nv_bfloat16* __restrict__ dst,
    int K, int is_weight, int total4)
{
    int gid = blockIdx.x * 256 + threadIdx.x;
    if (gid >= total4) return;
    const int kq = K >> 2;
    const int m  = gid / kq;
    const int k  = (gid - m * kq) << 2;

    float4 v = *(const float4*)(src + (size_t)m * K + k);
    float vv[4] = {v.x, v.y, v.z, v.w};
    unsigned short hib[4], lob[4];
    #pragma unroll
    for (int i = 0; i < 4; i++) {
        __nv_bfloat16 h = __float2bfloat16(vv[i]);
        __nv_bfloat16 l = __float2bfloat16(vv[i] - __bfloat162float(h));
        hib[i] = __bfloat16_as_ushort(h);
        lob[i] = __bfloat16_as_ushort(l);
    }
    uint2 hp = make_uint2((uint32_t)hib[0] | ((uint32_t)hib[1] << 16),
                          (uint32_t)hib[2] | ((uint32_t)hib[3] << 16));
    uint2 lp = make_uint2((uint32_t)lob[0] | ((uint32_t)lob[1] << 16),
                          (uint32_t)lob[2] | ((uint32_t)lob[3] << 16));

    const int ktiles = (3 * K) >> 6;
    const int mt = m >> 7, mr = m & 127;
    char* db = (char*)dst;

    #pragma unroll
    for (int copy = 0; copy < 3; copy++) {
        uint2 pk = (copy == 0) ? hp
                 : (copy == 1) ? (is_weight ? hp : lp)
                                : (is_weight ? lp : hp);
        int kk = k + copy * K;
        int kt = kk >> 6, c = kk & 63;
        size_t base = ((size_t)mt * ktiles + kt) * 16384;
        uint32_t off = (uint32_t)(mr * 128 + c * 2);
        off = off ^ ((off >> 3) & 0x70);
        *(uint2*)(db + base + off) = pk;
    }
}

// ---------------- bf16 mma.sync GEMM: C[M,N] = A'[M,K3] * B'[N,K3]^T ---------
// 256x128 CTA tile, 16 math warps (64x32 each) + 1 producer warp.
// mode 0: C = v (+bias) ; mode 1: C = E + relu(v+bias) ; mode 2: C = E + v + bias
#define G_STG    4
#define G_TB     16384                          // one 128x64 bf16 tile
#define G_STAGE  (3*G_TB)                       // A0 + A1 + B = 48KB
#define G_SMEM   (1024 + G_STG*G_STAGE)         // 197632

__global__ __launch_bounds__(544, 1) void gemm_mma(
    const __nv_bfloat16* __restrict__ A3, const __nv_bfloat16* __restrict__ B3,
    const float* __restrict__ bias, const float* __restrict__ E,
    float* __restrict__ C, int N, int K3, int mode)
{
    extern __shared__ char sm[];
    const uint32_t sb = smem_u32(sm);
    const int tid = threadIdx.x, wid = tid >> 5, lane = tid & 31;

    const uint32_t MFULL  = sb;            // G_STG x 8B
    const uint32_t MEMPTY = sb + 256;      // G_STG x 8B
    const uint32_t SPIPE  = sb + 1024;     // stage s: A0 | A1 | B

    if (tid == 0) {
        #pragma unroll
        for (int s = 0; s < G_STG; s++) { MBAR_INIT(MFULL + s*8, 1); MBAR_INIT(MEMPTY + s*8, 16); }
    }
    __syncthreads();

    const int ktiles = K3 >> 6;
    const int nt = blockIdx.x, mt = blockIdx.y;

    float d[4][4][4];
    #pragma unroll
    for (int a = 0; a < 4; a++)
        #pragma unroll
        for (int b = 0; b < 4; b++)
            #pragma unroll
            for (int c = 0; c < 4; c++) d[a][b][c] = 0.f;

    if (wid == 16) {
        // ---- producer ----
        if (elect_one()) {
            const char* A0 = (const char*)A3 + (size_t)(2*mt)   * ktiles * G_TB;
            const char* A1 = (const char*)A3 + (size_t)(2*mt+1) * ktiles * G_TB;
            const char* Bg = (const char*)B3 + (size_t)nt       * ktiles * G_TB;
            int s = 0, ph = 1;
            for (int kt = 0; kt < ktiles; kt++) {
                MBAR_WAIT(MEMPTY + s*8, ph);
                MBAR_EXPECT(MFULL + s*8, G_STAGE);
                const uint32_t dst = SPIPE + s*G_STAGE;
                BULK_G2S(dst,          A0 + (size_t)kt*G_TB, G_TB, MFULL + s*8);
                BULK_G2S(dst + G_TB,   A1 + (size_t)kt*G_TB, G_TB, MFULL + s*8);
                BULK_G2S(dst + 2*G_TB, Bg + (size_t)kt*G_TB, G_TB, MFULL + s*8);
                if (++s == G_STG) { s = 0; ph ^= 1; }
            }
        }
    } else {
        // ---- consumers: warp tile 64(M) x 32(N) ----
        const int wm = (wid & 3) * 64;           // 0,64,128,192
        const int wn = (wid >> 2) * 32;          // 0,32,64,96
        const uint32_t aTile  = (uint32_t)(wm >> 7) * G_TB;   // A0 or A1
        const uint32_t aLocal = (uint32_t)(wm & 127);

        const uint32_t rsub  = (uint32_t)(((lane >> 3) & 1) * 8 + (lane & 7));
        const uint32_t ksel  = (uint32_t)((lane >> 4) * 16);
        const uint32_t cmask = (uint32_t)((lane & 7) << 4);

        int s = 0, ph = 0;
        for (int kt = 0; kt < ktiles; kt++) {
            MBAR_WAIT(MFULL + s*8, ph);
            const uint32_t sa  = SPIPE + s*G_STAGE + aTile;
            const uint32_t sbb = SPIPE + s*G_STAGE + 2*G_TB;
            #pragma unroll
            for (int kk4 = 0; kk4 < 4; kk4++) {
                const uint32_t ko = (uint32_t)(kk4*32 + ksel) ^ cmask;
                uint32_t af[4][4];
                #pragma unroll
                for (int mi = 0; mi < 4; mi++)
                    LDSM_X4(af[mi][0], af[mi][1], af[mi][2], af[mi][3],
                            sa + (aLocal + mi*16 + rsub)*128 + ko);
                uint32_t bf[4][2];
                #pragma unroll
                for (int ng = 0; ng < 2; ng++) {
                    uint32_t t0, t1, t2, t3;
                    LDSM_X4(t0, t1, t2, t3,
                            sbb + (uint32_t)(wn + ng*16 + rsub)*128 + ko);
                    bf[2*ng][0] = t0; bf[2*ng+1][0] = t1;
                    bf[2*ng][1] = t2; bf[2*ng+1][1] = t3;
                }
                #pragma unroll
                for (int mi = 0; mi < 4; mi++)
                    #pragma unroll
                    for (int ni = 0; ni < 4; ni++)
                        MMA16816(d[mi][ni], af[mi], bf[ni]);
            }
            if (lane == 0) MBAR_ARRIVE(MEMPTY + s*8);
            if (++s == G_STG) { s = 0; ph ^= 1; }
        }
    }

    __syncthreads();

    // ---- epilogue: regs -> smem staging (256x132 fp32) -> coalesced fused store
    float* st = (float*)(sm + 1024);
    if (wid < 16) {
        const int wm = (wid & 3) * 64;
        const int wn = (wid >> 2) * 32;
        const int r0 = lane >> 2;
        const int cc = (lane & 3) * 2;
        #pragma unroll
        for (int mi = 0; mi < 4; mi++)
            #pragma unroll
            for (int ni = 0; ni < 4; ni++) {
                const int r = wm + mi*16 + r0;
                const int c = wn + ni*8 + cc;
                st[r*132 + c]       = d[mi][ni][0];
                st[r*132 + c + 1]   = d[mi][ni][1];
                st[(r+8)*132 + c]   = d[mi][ni][2];
                st[(r+8)*132 + c+1] = d[mi][ni][3];
            }
    }
    __syncthreads();

    if (tid < 512) {
        const int r0 = tid >> 5;            // 0..15
        const int c  = (tid & 31) * 4;
        const int n  = nt*128 + c;
        float4 bv = make_float4(0.f, 0.f, 0.f, 0.f);
        if (bias) bv = *(const float4*)(bias + n);
        #pragma unroll 4
        for (int rp = 0; rp < 16; rp++) {
            const int r = rp*16 + r0;
            const size_t idx = (size_t)(mt*256 + r) * N + n;
            float4 v = *(float4*)&st[r*132 + c];
            v.x += bv.x; v.y += bv.y; v.z += bv.z; v.w += bv.w;
            if (mode == 1) {
                float4 e = *(const float4*)(E + idx);
                v.x = e.x + fmaxf(v.x, 0.f); v.y = e.y + fmaxf(v.y, 0.f);
                v.z = e.z + fmaxf(v.z, 0.f); v.w = e.w + fmaxf(v.w, 0.f);
            } else if (mode == 2) {
                float4 e = *(const float4*)(E + idx);
                v.x += e.x; v.y += e.y; v.z += e.z; v.w += e.w;
            }
            *(float4*)(C + idx) = v;
        }
    }
}

// ---------------- causal flash attention (fp32) ------------------------------
#define BR 64
#define BC 64
__global__ __launch_bounds__(256) void attn_kernel(
    const float* __restrict__ qkv, float* __restrict__ out)
{
    extern __shared__ float smdyn[];
    float* Ks = smdyn;
    float* Vs = smdyn + 64*132;
    float* Sb = smdyn + 2*64*132;

    const int tid = threadIdx.x;
    const int qt  = blockIdx.x;
    const int hh  = blockIdx.y;
    const int bb  = blockIdx.z;
    const int q0  = qt * BR;

    const int r  = tid >> 2;
    const int g  = tid & 3;
    const int qi = q0 + r;

    float4 qreg[8];
    {
        const float* qp = qkv + (size_t)(bb*SS + qi) * QKVW + hh * HD;
        #pragma unroll
        for (int dd = 0; dd < 8; dd++) qreg[dd] = *(const float4*)(qp + (g + 4*dd) * 4);
    }

    float m = -INFINITY, l = 0.f;
    float4 acc[8];
    #pragma unroll
    for (int dd = 0; dd < 8; dd++) acc[dd] = make_float4(0.f,0.f,0.f,0.f);

    const int njt = q0 / BC + 1;
    for (int jt = 0; jt < njt; jt++) {
        const int j0 = jt * BC;
        __syncthreads();
        #pragma unroll
        for (int li = 0; li < 8; li++) {
            int id  = tid + li * 256;
            int rr  = id >> 5;
            int d4  = (id & 31) * 4;
            size_t gro = (size_t)(bb*SS + j0 + rr) * QKVW + hh * HD + d4;
            *(float4*)&Ks[rr*132 + d4] = *(const float4*)(qkv + gro + HH*HD);
            *(float4*)&Vs[rr*132 + d4] = *(const float4*)(qkv + gro + 2*HH*HD);
        }
        __syncthreads();

        #pragma unroll 4
        for (int c = 0; c < BC; c++) {
            const float4* kp = (const float4*)&Ks[c*132];
            float s = 0.f;
            #pragma unroll
            for (int dd = 0; dd < 8; dd++) {
                float4 kv = kp[g + 4*dd];
                s = fmaf(qreg[dd].x, kv.x, s); s = fmaf(qreg[dd].y, kv.y, s);
                s = fmaf(qreg[dd].z, kv.z, s); s = fmaf(qreg[dd].w, kv.w, s);
            }
            s += __shfl_xor_sync(0xffffffffu, s, 1);
            s += __shfl_xor_sync(0xffffffffu, s, 2);
            if (g == 0) {
                s *= 0.08838834764831845f;
                if (j0 + c > qi) s = -INFINITY;
                Sb[r*68 + c] = s;
            }
        }
        __syncwarp();

        float mNew = m;
        #pragma unroll 8
        for (int c = 0; c < BC; c++) mNew = fmaxf(mNew, Sb[r*68 + c]);
        float corr = __expf(m - mNew);
        m = mNew; l *= corr;
        #pragma unroll
        for (int dd = 0; dd < 8; dd++) {
            acc[dd].x *= corr; acc[dd].y *= corr; acc[dd].z *= corr; acc[dd].w *= corr;
        }
        #pragma unroll 2
        for (int c = 0; c < BC; c++) {
            float p = __expf(Sb[r*68 + c] - mNew);
            l += p;
            const float4* vp = (const float4*)&Vs[c*132];
            #pragma unroll
            for (int dd = 0; dd < 8; dd++) {
                float4 vv = vp[g + 4*dd];
                acc[dd].x = fmaf(p, vv.x, acc[dd].x); acc[dd].y = fmaf(p, vv.y, acc[dd].y);
                acc[dd].z = fmaf(p, vv.z, acc[dd].z); acc[dd].w = fmaf(p, vv.w, acc[dd].w);
            }
        }
    }

    const float inv = 1.f / l;
    const size_t obase = (size_t)((bb*HH + hh)*SS + qi) * HD;
    #pragma unroll
    for (int dd = 0; dd < 8; dd++) {
        float4 o = acc[dd];
        o.x *= inv; o.y *= inv; o.z *= inv; o.w *= inv;
        *(float4*)(out + obase + (g + 4*dd) * 4) = o;
    }
}

// ---------------- launch ------------------------------------------------------
static inline void conv(const float* s, __nv_bfloat16* d, int rows, int K, int isw) {
    int total4 = rows * (K >> 2);
    convert3<<<(total4 + 255) / 256, 256>>>(s, d, K, isw, total4);
}

extern "C" void kernel_launch(void* const* d_in, const int* in_sizes, int n_in,
                              void* d_out, int out_size)
{
    (void)in_sizes; (void)n_in; (void)out_size;
    const float* x     = (const float*)d_in[0];
    const float* rms_w = (const float*)d_in[1];
    const float* w_qkv = (const float*)d_in[2];
    const float* w_out = (const float*)d_in[3];
    const float* w1    = (const float*)d_in[4];
    const float* b1    = (const float*)d_in[5];
    const float* w3    = (const float*)d_in[6];
    const float* b3    = (const float*)d_in[7];
    const float* w2    = (const float*)d_in[8];
    const float* b2    = (const float*)d_in[9];
    float* out = (float*)d_out;

    float *xn,*qkv,*att,*h,*a1,*gg;
    cudaGetSymbolAddress((void**)&xn,  g_xn);
    cudaGetSymbolAddress((void**)&qkv, g_qkv);
    cudaGetSymbolAddress((void**)&att, g_att);
    cudaGetSymbolAddress((void**)&h,   g_h);
    cudaGetSymbolAddress((void**)&a1,  g_a1);
    cudaGetSymbolAddress((void**)&gg,  g_g);
    __nv_bfloat16 *xn3,*att3,*h3,*gg3,*wqkv3,*wout3,*w13,*w33,*w23;
    cudaGetSymbolAddress((void**)&xn3,   g_xn3);
    cudaGetSymbolAddress((void**)&att3,  g_att3);
    cudaGetSymbolAddress((void**)&h3,    g_h3);
    cudaGetSymbolAddress((void**)&gg3,   g_gg3);
    cudaGetSymbolAddress((void**)&wqkv3, g_wqkv3);
    cudaGetSymbolAddress((void**)&wout3, g_wout3);
    cudaGetSymbolAddress((void**)&w13,   g_w13);
    cudaGetSymbolAddress((void**)&w33,   g_w33);
    cudaGetSymbolAddress((void**)&w23,   g_w23);

    cudaFuncSetAttribute(gemm_mma, cudaFuncAttributeMaxDynamicSharedMemorySize, G_SMEM);
    const int attn_smem = (2*64*132 + 64*68) * (int)sizeof(float);
    cudaFuncSetAttribute(attn_kernel, cudaFuncAttributeMaxDynamicSharedMemorySize, attn_smem);

    // weight conversions (independent of activations)
    conv(w_qkv, wqkv3, QKVW, DD, 1);
    conv(w_out, wout3, DD,   DD, 1);
    conv(w1,    w13,   FF,   DD, 1);
    conv(w3,    w33,   FF,   DD, 1);
    conv(w2,    w23,   DD,   FF, 1);

    // 1) RMSNorm + convert
    rmsnorm_kernel<<<MM, 256>>>(x, rms_w, xn);
    conv(xn, xn3, MM, DD, 0);

    // 2) QKV projection
    gemm_mma<<<dim3(QKVW/128, MM/256), 544, G_SMEM>>>(xn3, wqkv3, nullptr, nullptr, qkv, QKVW, 3*DD, 0);

    // 3) attention
    attn_kernel<<<dim3(SS/BR, HH, BB), 256, attn_smem>>>(qkv, att);
    conv(att, att3, MM, DD, 0);

    // 4) out projection
    gemm_mma<<<dim3(DD/128, MM/256), 544, G_SMEM>>>(att3, wout3, nullptr, nullptr, h, DD, 3*DD, 0);
    conv(h, h3, MM, DD, 0);

    // 5) a1 = h @ w1^T + b1
    gemm_mma<<<dim3(FF/128, MM/256), 544, G_SMEM>>>(h3, w13, b1, nullptr, a1, FF, 3*DD, 0);

    // 6) g = a1 + relu(h @ w3^T + b3)
    gemm_mma<<<dim3(FF/128, MM/256), 544, G_SMEM>>>(h3, w33, b3, a1, gg, FF, 3*DD, 1);
    conv(gg, gg3, MM, FF, 0);

    // 7) out = x + g @ w2^T + b2
    gemm_mma<<<dim3(DD/128, MM/256), 544, G_SMEM>>>(gg3, w23, b2, x, out, DD, 3*FF, 2);
}

// round 5
// speedup vs baseline: 1.4540x; 1.4540x over previous
#include <cuda_runtime.h>
#include <cuda_bf16.h>
#include <math.h>
#include <stdint.h>

#define BB   2
#define SS   2048
#define DD   2048
#define HH   16
#define HD   128
#define FF   8192
#define MM   (BB*SS)          // 4096
#define QKVW (3*DD)           // 6144

// ---------------- fp32 scratch ----------------
__device__ float g_xn [MM*DD];
__device__ float g_qkv[MM*QKVW];
__device__ float g_att[MM*DD];
__device__ float g_h  [MM*DD];
__device__ float g_a1 [MM*FF];
__device__ float g_g  [MM*FF];

// ---------------- bf16 split scratch (tile-packed [rows/128][3K/64][128][64], SW128 swizzled)
__device__ __nv_bfloat16 g_xn3 [(size_t)MM*3*DD];
__device__ __nv_bfloat16 g_att3[(size_t)MM*3*DD];
__device__ __nv_bfloat16 g_h3  [(size_t)MM*3*DD];
__device__ __nv_bfloat16 g_gg3 [(size_t)MM*3*FF];
__device__ __nv_bfloat16 g_wqkv3[(size_t)QKVW*3*DD];
__device__ __nv_bfloat16 g_wout3[(size_t)DD*3*DD];
__device__ __nv_bfloat16 g_w13 [(size_t)FF*3*DD];
__device__ __nv_bfloat16 g_w33 [(size_t)FF*3*DD];
__device__ __nv_bfloat16 g_w23 [(size_t)DD*3*FF];

// ---------------- PTX helpers (sm_90 baseline features only) -----------------
__device__ __forceinline__ uint32_t smem_u32(const void* p) {
    uint32_t a;
    asm("{ .reg .u64 t; cvta.to.shared.u64 t, %1; cvt.u32.u64 %0, t; }" : "=r"(a) : "l"(p));
    return a;
}
__device__ __forceinline__ uint32_t elect_one() {
    uint32_t p;
    asm volatile("{ .reg .pred p; elect.sync _|p, 0xFFFFFFFF; selp.b32 %0,1,0,p; }" : "=r"(p));
    return p;
}
__device__ __forceinline__ float to_tf32(float x) {
    uint32_t t;
    asm("cvt.rna.tf32.f32 %0, %1;" : "=r"(t) : "f"(x));
    return __uint_as_float(t);
}
#define MBAR_INIT(a, c) \
    asm volatile("mbarrier.init.shared.b64 [%0], %1;" :: "r"(a), "r"(c) : "memory")
#define MBAR_EXPECT(a, b) \
    asm volatile("mbarrier.arrive.expect_tx.shared.b64 _, [%0], %1;" :: "r"(a), "r"(b) : "memory")
#define MBAR_ARRIVE(a) \
    asm volatile("mbarrier.arrive.shared.b64 _, [%0];" :: "r"(a) : "memory")
#define MBAR_WAIT(a, ph) do { uint32_t _m=(a), _p=(ph), _d;                                   \
    asm volatile("{ .reg .pred p; mbarrier.try_wait.parity.acquire.cta.shared::cta.b64 p, [%1], %2; selp.b32 %0,1,0,p; }" \
                 : "=r"(_d) : "r"(_m), "r"(_p) : "memory");                                   \
    if (!_d) {                                                                                \
      asm volatile("{ .reg .pred P1; WL%=: mbarrier.try_wait.parity.acquire.cta.shared::cta.b64 P1, [%0], %1, 0x989680; @P1 bra.uni WD%=; bra.uni WL%=; WD%=: }" \
                   :: "r"(_m), "r"(_p) : "memory"); } } while(0)
#define BULK_G2S(d, s, n, m) \
    asm volatile("cp.async.bulk.shared::cta.global.mbarrier::complete_tx::bytes [%0], [%1], %2, [%3];" \
                 :: "r"(d), "l"(s), "r"(n), "r"(m) : "memory")
#define LDSM_X4(r0, r1, r2, r3, a) \
    asm volatile("ldmatrix.sync.aligned.m8n8.x4.shared.b16 {%0,%1,%2,%3}, [%4];" \
                 : "=r"(r0), "=r"(r1), "=r"(r2), "=r"(r3) : "r"(a))
#define MMA16816(d, av, bv) \
    asm volatile("mma.sync.aligned.m16n8k16.row.col.f32.bf16.bf16.f32 " \
                 "{%0,%1,%2,%3}, {%4,%5,%6,%7}, {%8,%9}, {%0,%1,%2,%3};" \
                 : "+f"((d)[0]), "+f"((d)[1]), "+f"((d)[2]), "+f"((d)[3]) \
                 : "r"((av)[0]), "r"((av)[1]), "r"((av)[2]), "r"((av)[3]), \
                   "r"((bv)[0]), "r"((bv)[1]))
#define MMA1688TF(d, a0, a1, a2, a3, b0, b1) \
    asm volatile("mma.sync.aligned.m16n8k8.row.col.f32.tf32.tf32.f32 " \
                 "{%0,%1,%2,%3}, {%4,%5,%6,%7}, {%8,%9}, {%0,%1,%2,%3};" \
                 : "+f"((d)[0]), "+f"((d)[1]), "+f"((d)[2]), "+f"((d)[3]) \
                 : "r"(a0), "r"(a1), "r"(a2), "r"(a3), "r"(b0), "r"(b1))

// ---------------- RMSNorm ----------------------------------------------------
__global__ __launch_bounds__(256) void rmsnorm_kernel(
    const float* __restrict__ x, const float* __restrict__ w, float* __restrict__ out)
{
    const int row = blockIdx.x;
    const float* xr = x + (size_t)row * DD;
    float ss = 0.f;
    for (int i = threadIdx.x; i < DD; i += 256) { float v = xr[i]; ss = fmaf(v, v, ss); }
    #pragma unroll
    for (int o = 16; o; o >>= 1) ss += __shfl_xor_sync(0xffffffffu, ss, o);
    __shared__ float sred[8];
    if ((threadIdx.x & 31) == 0) sred[threadIdx.x >> 5] = ss;
    __syncthreads();
    float tot = sred[0]+sred[1]+sred[2]+sred[3]+sred[4]+sred[5]+sred[6]+sred[7];
    float sc = rsqrtf(tot * (1.0f / DD) + 1e-5f);
    float* orow = out + (size_t)row * DD;
    for (int i = threadIdx.x; i < DD; i += 256) orow[i] = xr[i] * sc * w[i];
}

// ---------------- fp32 -> bf16 hi/lo split, tile-packed, pre-swizzled --------
__global__ __launch_bounds__(256) void convert3(
    const float* __restrict__ src, __nv_bfloat16* __restrict__ dst,
    int K, int is_weight, int total4)
{
    int gid = blockIdx.x * 256 + threadIdx.x;
    if (gid >= total4) return;
    const int kq = K >> 2;
    const int m  = gid / kq;
    const int k  = (gid - m * kq) << 2;

    float4 v = *(const float4*)(src + (size_t)m * K + k);
    float vv[4] = {v.x, v.y, v.z, v.w};
    unsigned short hib[4], lob[4];
    #pragma unroll
    for (int i = 0; i < 4; i++) {
        __nv_bfloat16 h = __float2bfloat16(vv[i]);
        __nv_bfloat16 l = __float2bfloat16(vv[i] - __bfloat162float(h));
        hib[i] = __bfloat16_as_ushort(h);
        lob[i] = __bfloat16_as_ushort(l);
    }
    uint2 hp = make_uint2((uint32_t)hib[0] | ((uint32_t)hib[1] << 16),
                          (uint32_t)hib[2] | ((uint32_t)hib[3] << 16));
    uint2 lp = make_uint2((uint32_t)lob[0] | ((uint32_t)lob[1] << 16),
                          (uint32_t)lob[2] | ((uint32_t)lob[3] << 16));

    const int ktiles = (3 * K) >> 6;
    const int mt = m >> 7, mr = m & 127;
    char* db = (char*)dst;

    #pragma unroll
    for (int copy = 0; copy < 3; copy++) {
        uint2 pk = (copy == 0) ? hp
                 : (copy == 1) ? (is_weight ? hp : lp)
                                : (is_weight ? lp : hp);
        int kk = k + copy * K;
        int kt = kk >> 6, c = kk & 63;
        size_t base = ((size_t)mt * ktiles + kt) * 16384;
        uint32_t off = (uint32_t)(mr * 128 + c * 2);
        off = off ^ ((off >> 3) & 0x70);
        *(uint2*)(db + base + off) = pk;
    }
}

// ---------------- bf16 mma.sync GEMM (round-3 config + CTA swizzle) ----------
#define G_STG    4
#define G_TB     16384
#define G_SMEM   (1024 + G_STG*2*G_TB)         // 132096
#define GROUP_M  8

__global__ __launch_bounds__(288, 1) void gemm_mma(
    const __nv_bfloat16* __restrict__ A3, const __nv_bfloat16* __restrict__ B3,
    const float* __restrict__ bias, const float* __restrict__ E,
    float* __restrict__ C, int N, int K3, int mode)
{
    extern __shared__ char sm[];
    const uint32_t sb = smem_u32(sm);
    const int tid = threadIdx.x, wid = tid >> 5, lane = tid & 31;

    const uint32_t MFULL  = sb;
    const uint32_t MEMPTY = sb + 256;
    const uint32_t SA     = sb + 1024;
    const uint32_t SBq    = SA + G_STG * G_TB;

    if (tid == 0) {
        #pragma unroll
        for (int s = 0; s < G_STG; s++) { MBAR_INIT(MFULL + s*8, 1); MBAR_INIT(MEMPTY + s*8, 8); }
    }
    __syncthreads();

    const int ktiles = K3 >> 6;
    // ---- CTA swizzle: GROUP_M m-rows per group, nt varies slowest in group
    const int gridN = gridDim.x;
    const int bid   = blockIdx.y * gridN + blockIdx.x;
    const int tpg   = GROUP_M * gridN;
    const int grp   = bid / tpg, rem = bid - grp * tpg;
    const int mt    = grp * GROUP_M + (rem % GROUP_M);
    const int nt    = rem / GROUP_M;

    float d[2][8][4];
    #pragma unroll
    for (int a = 0; a < 2; a++)
        #pragma unroll
        for (int b = 0; b < 8; b++)
            #pragma unroll
            for (int c = 0; c < 4; c++) d[a][b][c] = 0.f;

    if (wid == 8) {
        if (elect_one()) {
            const char* Ag = (const char*)A3 + (size_t)mt * ktiles * G_TB;
            const char* Bg = (const char*)B3 + (size_t)nt * ktiles * G_TB;
            int s = 0, ph = 1;
            for (int kt = 0; kt < ktiles; kt++) {
                MBAR_WAIT(MEMPTY + s*8, ph);
                MBAR_EXPECT(MFULL + s*8, 2*G_TB);
                BULK_G2S(SA  + s*G_TB, Ag + (size_t)kt*G_TB, G_TB, MFULL + s*8);
                BULK_G2S(SBq + s*G_TB, Bg + (size_t)kt*G_TB, G_TB, MFULL + s*8);
                if (++s == G_STG) { s = 0; ph ^= 1; }
            }
        }
    } else {
        const int wm = (wid & 3) * 32;
        const int wn = (wid >> 2) * 64;
        const uint32_t rsub   = (uint32_t)(((lane >> 3) & 1) * 8 + (lane & 7));
        const uint32_t ksel   = (uint32_t)((lane >> 4) * 16);
        const uint32_t cmask  = (uint32_t)((lane & 7) << 4);
        const uint32_t aRowOff = (uint32_t)(wm + rsub) * 128;
        const uint32_t bRowOff = (uint32_t)(wn + rsub) * 128;

        int s = 0, ph = 0;
        for (int kt = 0; kt < ktiles; kt++) {
            MBAR_WAIT(MFULL + s*8, ph);
            const uint32_t sa  = SA  + s*G_TB;
            const uint32_t sbb = SBq + s*G_TB;
            #pragma unroll
            for (int kk4 = 0; kk4 < 4; kk4++) {
                const uint32_t ko = (uint32_t)(kk4*32 + ksel) ^ cmask;
                uint32_t af[2][4];
                #pragma unroll
                for (int mi = 0; mi < 2; mi++)
                    LDSM_X4(af[mi][0], af[mi][1], af[mi][2], af[mi][3],
                            sa + aRowOff + mi*2048 + ko);
                uint32_t bf[8][2];
                #pragma unroll
                for (int ng = 0; ng < 4; ng++) {
                    uint32_t t0, t1, t2, t3;
                    LDSM_X4(t0, t1, t2, t3, sbb + bRowOff + ng*2048 + ko);
                    bf[2*ng][0] = t0; bf[2*ng+1][0] = t1;
                    bf[2*ng][1] = t2; bf[2*ng+1][1] = t3;
                }
                #pragma unroll
                for (int mi = 0; mi < 2; mi++)
                    #pragma unroll
                    for (int ni = 0; ni < 8; ni++)
                        MMA16816(d[mi][ni], af[mi], bf[ni]);
            }
            if (lane == 0) MBAR_ARRIVE(MEMPTY + s*8);
            if (++s == G_STG) { s = 0; ph ^= 1; }
        }
    }

    __syncthreads();

    float* st = (float*)(sm + 1024);
    if (wid < 8) {
        const int wm = (wid & 3) * 32;
        const int wn = (wid >> 2) * 64;
        const int r0 = lane >> 2;
        const int cc = (lane & 3) * 2;
        #pragma unroll
        for (int mi = 0; mi < 2; mi++)
            #pragma unroll
            for (int ni = 0; ni < 8; ni++) {
                const int r = wm + mi*16 + r0;
                const int c = wn + ni*8 + cc;
                st[r*132 + c]       = d[mi][ni][0];
                st[r*132 + c + 1]   = d[mi][ni][1];
                st[(r+8)*132 + c]   = d[mi][ni][2];
                st[(r+8)*132 + c+1] = d[mi][ni][3];
            }
    }
    __syncthreads();

    if (tid < 256) {
        const int r0 = tid >> 5;
        const int c  = (tid & 31) * 4;
        const int n  = nt*128 + c;
        float4 bv = make_float4(0.f, 0.f, 0.f, 0.f);
        if (bias) bv = *(const float4*)(bias + n);
        #pragma unroll 4
        for (int rp = 0; rp < 16; rp++) {
            const int r = rp*8 + r0;
            const size_t idx = (size_t)(mt*128 + r) * N + n;
            float4 v = *(float4*)&st[r*132 + c];
            v.x += bv.x; v.y += bv.y; v.z += bv.z; v.w += bv.w;
            if (mode == 1) {
                float4 e = *(const float4*)(E + idx);
                v.x = e.x + fmaxf(v.x, 0.f); v.y = e.y + fmaxf(v.y, 0.f);
                v.z = e.z + fmaxf(v.z, 0.f); v.w = e.w + fmaxf(v.w, 0.f);
            } else if (mode == 2) {
                float4 e = *(const float4*)(E + idx);
                v.x += e.x; v.y += e.y; v.z += e.z; v.w += e.w;
            }
            *(float4*)(C + idx) = v;
        }
    }
}

// ---------------- tf32 tensor-core causal flash attention --------------------
// 64 q-rows x 64 keys per iteration, HD=128, 8 warps.
// QK warps: 4 over q (16 rows), 2 over keys (32). PV warps: 4 over q, 2 over hd (64).
#define AT_SMEMF (3*64*132 + 64*68 + 128)
__global__ __launch_bounds__(256) void attn_tc(
    const float* __restrict__ qkv, float* __restrict__ out)
{
    extern __shared__ float s[];
    float* Qs = s;                 // 64 x 132 (tf32 vals, pre-scaled)
    float* Ks = Qs + 64*132;       // 64 x 132 (tf32)
    float* Vs = Ks + 64*132;       // 64 x 132 (tf32)
    float* Sb = Vs + 64*132;       // 64 x 68 scores / p
    float* Cr = Sb + 64*68;        // 64 corr
    float* Ll = Cr + 64;           // 64 l

    const int tid = threadIdx.x, wid = tid >> 5, lane = tid & 31;
    const int qt = blockIdx.x, hh = blockIdx.y, bb = blockIdx.z;
    const int q0 = qt * 64;

    // load Q (scaled by 1/sqrt(HD), tf32-rounded)
    #pragma unroll
    for (int i = 0; i < 8; i++) {
        int id = i*256 + tid;
        int rr = id >> 5, c4 = (id & 31) * 4;
        float4 v = *(const float4*)(qkv + (size_t)(bb*SS + q0 + rr) * QKVW + hh*HD + c4);
        Qs[rr*132 + c4 + 0] = to_tf32(v.x * 0.08838834764831845f);
        Qs[rr*132 + c4 + 1] = to_tf32(v.y * 0.08838834764831845f);
        Qs[rr*132 + c4 + 2] = to_tf32(v.z * 0.08838834764831845f);
        Qs[rr*132 + c4 + 3] = to_tf32(v.w * 0.08838834764831845f);
    }

    // per-row softmax state (4 replicated lanes per row)
    const int srow = tid >> 2;      // 0..63
    const int sg   = tid & 3;       // 0..3
    float mrun = -INFINITY, lrun = 0.f;

    // PV accumulators: warp tile 16(q) x 64(hd); 8 n-tiles x 4 regs
    float o[8][4];
    #pragma unroll
    for (int i = 0; i < 8; i++)
        #pragma unroll
        for (int j = 0; j < 4; j++) o[i][j] = 0.f;

    const int wm  = (wid & 3) * 16;          // q offset (both phases)
    const int wnk = (wid >> 2) * 32;         // key offset (QK phase)
    const int wnv = (wid >> 2) * 64;         // hd offset (PV phase)
    const int rA0 = wm + lane/4, rA1 = rA0 + 8;

    const int njt = qt + 1;
    for (int jt = 0; jt < njt; jt++) {
        const int j0 = jt * 64;
        __syncthreads();                      // protect K/V/Sb from prior consumers
        // load K, V tiles (tf32)
        #pragma unroll
        for (int i = 0; i < 8; i++) {
            int id = i*256 + tid;
            int rr = id >> 5, c4 = (id & 31) * 4;
            size_t base = (size_t)(bb*SS + j0 + rr) * QKVW + hh*HD + c4;
            float4 kv = *(const float4*)(qkv + base + HH*HD);
            float4 vv = *(const float4*)(qkv + base + 2*HH*HD);
            Ks[rr*132 + c4 + 0] = to_tf32(kv.x); Ks[rr*132 + c4 + 1] = to_tf32(kv.y);
            Ks[rr*132 + c4 + 2] = to_tf32(kv.z); Ks[rr*132 + c4 + 3] = to_tf32(kv.w);
            Vs[rr*132 + c4 + 0] = to_tf32(vv.x); Vs[rr*132 + c4 + 1] = to_tf32(vv.y);
            Vs[rr*132 + c4 + 2] = to_tf32(vv.z); Vs[rr*132 + c4 + 3] = to_tf32(vv.w);
        }
        __syncthreads();

        // ---- QK^T: scores tile 64x64
        {
            float c[4][4];
            #pragma unroll
            for (int i = 0; i < 4; i++)
                #pragma unroll
                for (int j = 0; j < 4; j++) c[i][j] = 0.f;
            #pragma unroll
            for (int ks = 0; ks < 16; ks++) {
                const int k0 = ks*8 + (lane & 3);
                uint32_t a0 = __float_as_uint(Qs[rA0*132 + k0]);
                uint32_t a1 = __float_as_uint(Qs[rA1*132 + k0]);
                uint32_t a2 = __float_as_uint(Qs[rA0*132 + k0 + 4]);
                uint32_t a3 = __float_as_uint(Qs[rA1*132 + k0 + 4]);
                #pragma unroll
                for (int ntl = 0; ntl < 4; ntl++) {
                    const int nrow = wnk + ntl*8 + lane/4;
                    uint32_t b0 = __float_as_uint(Ks[nrow*132 + k0]);
                    uint32_t b1 = __float_as_uint(Ks[nrow*132 + k0 + 4]);
                    MMA1688TF(c[ntl], a0, a1, a2, a3, b0, b1);
                }
            }
            const int cc = (lane & 3) * 2;
            #pragma unroll
            for (int ntl = 0; ntl < 4; ntl++) {
                const int cb = wnk + ntl*8 + cc;
                Sb[rA0*68 + cb]     = c[ntl][0];
                Sb[rA0*68 + cb + 1] = c[ntl][1];
                Sb[rA1*68 + cb]     = c[ntl][2];
                Sb[rA1*68 + cb + 1] = c[ntl][3];
            }
        }
        __syncthreads();

        // ---- online softmax (4 lanes per row, interleaved columns)
        {
            const bool diag = (jt == qt);
            const int qi_rel = srow;         // query index within tile == global - q0; j0==q0 on diag
            float mx = -INFINITY;
            float pv[16];
            #pragma unroll
            for (int j = 0; j < 16; j++) {
                const int c = sg + 4*j;
                float v = Sb[srow*68 + c];
                if (diag && c > qi_rel) v = -INFINITY;
                pv[j] = v;
                mx = fmaxf(mx, v);
            }
            mx = fmaxf(mx, __shfl_xor_sync(0xffffffffu, mx, 1));
            mx = fmaxf(mx, __shfl_xor_sync(0xffffffffu, mx, 2));
            const float mNew = fmaxf(mrun, mx);
            const float corr = __expf(mrun - mNew);
            float ls = 0.f;
            #pragma unroll
            for (int j = 0; j < 16; j++) {
                const int c = sg + 4*j;
                float p = (pv[j] == -INFINITY) ? 0.f : to_tf32(__expf(pv[j] - mNew));
                Sb[srow*68 + c] = p;
                ls += p;
            }
            ls += __shfl_xor_sync(0xffffffffu, ls, 1);
            ls += __shfl_xor_sync(0xffffffffu, ls, 2);
            lrun = lrun * corr + ls;
            mrun = mNew;
            if (sg == 0) { Cr[srow] = corr; Ll[srow] = lrun; }
        }
        __syncthreads();

        // ---- PV: out += P[64x64] @ V[64x128]
        {
            const float c0 = Cr[rA0], c1 = Cr[rA1];
            #pragma unroll
            for (int i = 0; i < 8; i++) {
                o[i][0] *= c0; o[i][1] *= c0;
                o[i][2] *= c1; o[i][3] *= c1;
            }
            #pragma unroll
            for (int ks = 0; ks < 8; ks++) {
                const int k0 = ks*8 + (lane & 3);
                uint32_t a0 = __float_as_uint(Sb[rA0*68 + k0]);
                uint32_t a1 = __float_as_uint(Sb[rA1*68 + k0]);
                uint32_t a2 = __float_as_uint(Sb[rA0*68 + k0 + 4]);
                uint32_t a3 = __float_as_uint(Sb[rA1*68 + k0 + 4]);
                #pragma unroll
                for (int ntl = 0; ntl < 8; ntl++) {
                    const int ncol = wnv + ntl*8 + lane/4;
                    uint32_t b0 = __float_as_uint(Vs[k0*132 + ncol]);
                    uint32_t b1 = __float_as_uint(Vs[(k0+4)*132 + ncol]);
                    MMA1688TF(o[ntl], a0, a1, a2, a3, b0, b1);
                }
            }
        }
    }
    __syncthreads();

    // ---- normalize + store ([B][H][S][HD] raw-reshape layout)
    {
        const float inv0 = 1.f / Ll[rA0];
        const float inv1 = 1.f / Ll[rA1];
        const size_t ob0 = (size_t)((bb*HH + hh)*SS + q0 + rA0) * HD;
        const size_t ob1 = (size_t)((bb*HH + hh)*SS + q0 + rA1) * HD;
        const int cc = (lane & 3) * 2;
        #pragma unroll
        for (int ntl = 0; ntl < 8; ntl++) {
            const int cb = wnv + ntl*8 + cc;
            *(float2*)(out + ob0 + cb) = make_float2(o[ntl][0]*inv0, o[ntl][1]*inv0);
            *(float2*)(out + ob1 + cb) = make_float2(o[ntl][2]*inv1, o[ntl][3]*inv1);
        }
    }
}

// ---------------- launch ------------------------------------------------------
static inline void conv(const float* s, __nv_bfloat16* d, int rows, int K, int isw) {
    int total4 = rows * (K >> 2);
    convert3<<<(total4 + 255) / 256, 256>>>(s, d, K, isw, total4);
}

extern "C" void kernel_launch(void* const* d_in, const int* in_sizes, int n_in,
                              void* d_out, int out_size)
{
    (void)in_sizes; (void)n_in; (void)out_size;
    const float* x     = (const float*)d_in[0];
    const float* rms_w = (const float*)d_in[1];
    const float* w_qkv = (const float*)d_in[2];
    const float* w_out = (const float*)d_in[3];
    const float* w1    = (const float*)d_in[4];
    const float* b1    = (const float*)d_in[5];
    const float* w3    = (const float*)d_in[6];
    const float* b3    = (const float*)d_in[7];
    const float* w2    = (const float*)d_in[8];
    const float* b2    = (const float*)d_in[9];
    float* out = (float*)d_out;

    float *xn,*qkv,*att,*h,*a1,*gg;
    cudaGetSymbolAddress((void**)&xn,  g_xn);
    cudaGetSymbolAddress((void**)&qkv, g_qkv);
    cudaGetSymbolAddress((void**)&att, g_att);
    cudaGetSymbolAddress((void**)&h,   g_h);
    cudaGetSymbolAddress((void**)&a1,  g_a1);
    cudaGetSymbolAddress((void**)&gg,  g_g);
    __nv_bfloat16 *xn3,*att3,*h3,*gg3,*wqkv3,*wout3,*w13,*w33,*w23;
    cudaGetSymbolAddress((void**)&xn3,   g_xn3);
    cudaGetSymbolAddress((void**)&att3,  g_att3);
    cudaGetSymbolAddress((void**)&h3,    g_h3);
    cudaGetSymbolAddress((void**)&gg3,   g_gg3);
    cudaGetSymbolAddress((void**)&wqkv3, g_wqkv3);
    cudaGetSymbolAddress((void**)&wout3, g_wout3);
    cudaGetSymbolAddress((void**)&w13,   g_w13);
    cudaGetSymbolAddress((void**)&w33,   g_w33);
    cudaGetSymbolAddress((void**)&w23,   g_w23);

    cudaFuncSetAttribute(gemm_mma, cudaFuncAttributeMaxDynamicSharedMemorySize, G_SMEM);
    const int attn_smem = AT_SMEMF * (int)sizeof(float);
    cudaFuncSetAttribute(attn_tc, cudaFuncAttributeMaxDynamicSharedMemorySize, attn_smem);

    // weight conversions
    conv(w_qkv, wqkv3, QKVW, DD, 1);
    conv(w_out, wout3, DD,   DD, 1);
    conv(w1,    w13,   FF,   DD, 1);
    conv(w3,    w33,   FF,   DD, 1);
    conv(w2,    w23,   DD,   FF, 1);

    // 1) RMSNorm + convert
    rmsnorm_kernel<<<MM, 256>>>(x, rms_w, xn);
    conv(xn, xn3, MM, DD, 0);

    // 2) QKV projection
    gemm_mma<<<dim3(QKVW/128, MM/128), 288, G_SMEM>>>(xn3, wqkv3, nullptr, nullptr, qkv, QKVW, 3*DD, 0);

    // 3) attention (tf32 tensor cores)
    attn_tc<<<dim3(SS/64, HH, BB), 256, attn_smem>>>(qkv, att);
    conv(att, att3, MM, DD, 0);

    // 4) out projection
    gemm_mma<<<dim3(DD/128, MM/128), 288, G_SMEM>>>(att3, wout3, nullptr, nullptr, h, DD, 3*DD, 0);
    conv(h, h3, MM, DD, 0);

    // 5) a1 = h @ w1^T + b1
    gemm_mma<<<dim3(FF/128, MM/128), 288, G_SMEM>>>(h3, w13, b1, nullptr, a1, FF, 3*DD, 0);

    // 6) g = a1 + relu(h @ w3^T + b3)
    gemm_mma<<<dim3(FF/128, MM/128), 288, G_SMEM>>>(h3, w33, b3, a1, gg, FF, 3*DD, 1);
    conv(gg, gg3, MM, FF, 0);

    // 7) out = x + g @ w2^T + b2
    gemm_mma<<<dim3(DD/128, MM/128), 288, G_SMEM>>>(gg3, w23, b2, x, out, DD, 3*FF, 2);
}

// round 6
// speedup vs baseline: 1.9794x; 1.3614x over previous
#include <cuda_runtime.h>
#include <cuda_fp16.h>
#include <math.h>
#include <stdint.h>

#define BB   2
#define SS   2048
#define DD   2048
#define HH   16
#define HD   128
#define FF   8192
#define MM   (BB*SS)          // 4096
#define QKVW (3*DD)           // 6144

// ---------------- fp32 scratch ----------------
__device__ float g_xn [MM*DD];
__device__ float g_qkv[MM*QKVW];
__device__ float g_att[MM*DD];
__device__ float g_h  [MM*DD];
__device__ float g_a1 [MM*FF];
__device__ float g_g  [MM*FF];

// ---------------- fp16 2-term split scratch (tile-packed [rows/128][2K/64][128][64], SW128 swizzled)
__device__ __half g_xn2 [(size_t)MM*2*DD];
__device__ __half g_att2[(size_t)MM*2*DD];
__device__ __half g_h2  [(size_t)MM*2*DD];
__device__ __half g_gg2 [(size_t)MM*2*FF];
__device__ __half g_wqkv2[(size_t)QKVW*2*DD];
__device__ __half g_wout2[(size_t)DD*2*DD];
__device__ __half g_w12 [(size_t)FF*2*DD];
__device__ __half g_w32 [(size_t)FF*2*DD];
__device__ __half g_w22 [(size_t)DD*2*FF];

// ---------------- PTX helpers (sm_90 baseline features only) -----------------
__device__ __forceinline__ uint32_t smem_u32(const void* p) {
    uint32_t a;
    asm("{ .reg .u64 t; cvta.to.shared.u64 t, %1; cvt.u32.u64 %0, t; }" : "=r"(a) : "l"(p));
    return a;
}
__device__ __forceinline__ uint32_t elect_one() {
    uint32_t p;
    asm volatile("{ .reg .pred p; elect.sync _|p, 0xFFFFFFFF; selp.b32 %0,1,0,p; }" : "=r"(p));
    return p;
}
__device__ __forceinline__ float to_tf32(float x) {
    uint32_t t;
    asm("cvt.rna.tf32.f32 %0, %1;" : "=r"(t) : "f"(x));
    return __uint_as_float(t);
}
#define MBAR_INIT(a, c) \
    asm volatile("mbarrier.init.shared.b64 [%0], %1;" :: "r"(a), "r"(c) : "memory")
#define MBAR_EXPECT(a, b) \
    asm volatile("mbarrier.arrive.expect_tx.shared.b64 _, [%0], %1;" :: "r"(a), "r"(b) : "memory")
#define MBAR_ARRIVE(a) \
    asm volatile("mbarrier.arrive.shared.b64 _, [%0];" :: "r"(a) : "memory")
#define MBAR_WAIT(a, ph) do { uint32_t _m=(a), _p=(ph), _d;                                   \
    asm volatile("{ .reg .pred p; mbarrier.try_wait.parity.acquire.cta.shared::cta.b64 p, [%1], %2; selp.b32 %0,1,0,p; }" \
                 : "=r"(_d) : "r"(_m), "r"(_p) : "memory");                                   \
    if (!_d) {                                                                                \
      asm volatile("{ .reg .pred P1; WL%=: mbarrier.try_wait.parity.acquire.cta.shared::cta.b64 P1, [%0], %1, 0x989680; @P1 bra.uni WD%=; bra.uni WL%=; WD%=: }" \
                   :: "r"(_m), "r"(_p) : "memory"); } } while(0)
#define BULK_G2S(d, s, n, m) \
    asm volatile("cp.async.bulk.shared::cta.global.mbarrier::complete_tx::bytes [%0], [%1], %2, [%3];" \
                 :: "r"(d), "l"(s), "r"(n), "r"(m) : "memory")
#define LDSM_X4(r0, r1, r2, r3, a) \
    asm volatile("ldmatrix.sync.aligned.m8n8.x4.shared.b16 {%0,%1,%2,%3}, [%4];" \
                 : "=r"(r0), "=r"(r1), "=r"(r2), "=r"(r3) : "r"(a))
#define MMA16816H(d, av, bv) \
    asm volatile("mma.sync.aligned.m16n8k16.row.col.f32.f16.f16.f32 " \
                 "{%0,%1,%2,%3}, {%4,%5,%6,%7}, {%8,%9}, {%0,%1,%2,%3};" \
                 : "+f"((d)[0]), "+f"((d)[1]), "+f"((d)[2]), "+f"((d)[3]) \
                 : "r"((av)[0]), "r"((av)[1]), "r"((av)[2]), "r"((av)[3]), \
                   "r"((bv)[0]), "r"((bv)[1]))
#define MMA1688TF(d, a0, a1, a2, a3, b0, b1) \
    asm volatile("mma.sync.aligned.m16n8k8.row.col.f32.tf32.tf32.f32 " \
                 "{%0,%1,%2,%3}, {%4,%5,%6,%7}, {%8,%9}, {%0,%1,%2,%3};" \
                 : "+f"((d)[0]), "+f"((d)[1]), "+f"((d)[2]), "+f"((d)[3]) \
                 : "r"(a0), "r"(a1), "r"(a2), "r"(a3), "r"(b0), "r"(b1))

// ---------------- RMSNorm ----------------------------------------------------
__global__ __launch_bounds__(256) void rmsnorm_kernel(
    const float* __restrict__ x, const float* __restrict__ w, float* __restrict__ out)
{
    const int row = blockIdx.x;
    const float* xr = x + (size_t)row * DD;
    float ss = 0.f;
    for (int i = threadIdx.x; i < DD; i += 256) { float v = xr[i]; ss = fmaf(v, v, ss); }
    #pragma unroll
    for (int o = 16; o; o >>= 1) ss += __shfl_xor_sync(0xffffffffu, ss, o);
    __shared__ float sred[8];
    if ((threadIdx.x & 31) == 0) sred[threadIdx.x >> 5] = ss;
    __syncthreads();
    float tot = sred[0]+sred[1]+sred[2]+sred[3]+sred[4]+sred[5]+sred[6]+sred[7];
    float sc = rsqrtf(tot * (1.0f / DD) + 1e-5f);
    float* orow = out + (size_t)row * DD;
    for (int i = threadIdx.x; i < DD; i += 256) orow[i] = xr[i] * sc * w[i];
}

// ---------------- fp32 -> fp16 2-term split, tile-packed, pre-swizzled -------
// activations: copies along K' are (hi, lo) ; weights: (hi, hi)
__global__ __launch_bounds__(256) void convert2(
    const float* __restrict__ src, __half* __restrict__ dst,
    int K, int is_weight, int total4)
{
    int gid = blockIdx.x * 256 + threadIdx.x;
    if (gid >= total4) return;
    const int kq = K >> 2;
    const int m  = gid / kq;
    const int k  = (gid - m * kq) << 2;

    float4 v = *(const float4*)(src + (size_t)m * K + k);
    float vv[4] = {v.x, v.y, v.z, v.w};
    unsigned short hib[4], lob[4];
    #pragma unroll
    for (int i = 0; i < 4; i++) {
        __half h = __float2half_rn(vv[i]);
        __half l = __float2half_rn(vv[i] - __half2float(h));
        hib[i] = __half_as_ushort(h);
        lob[i] = __half_as_ushort(l);
    }
    uint2 hp = make_uint2((uint32_t)hib[0] | ((uint32_t)hib[1] << 16),
                          (uint32_t)hib[2] | ((uint32_t)hib[3] << 16));
    uint2 lp = make_uint2((uint32_t)lob[0] | ((uint32_t)lob[1] << 16),
                          (uint32_t)lob[2] | ((uint32_t)lob[3] << 16));

    const int ktiles = (2 * K) >> 6;
    const int mt = m >> 7, mr = m & 127;
    char* db = (char*)dst;

    #pragma unroll
    for (int copy = 0; copy < 2; copy++) {
        uint2 pk = (copy == 0) ? hp : (is_weight ? hp : lp);
        int kk = k + copy * K;
        int kt = kk >> 6, c = kk & 63;
        size_t base = ((size_t)mt * ktiles + kt) * 16384;
        uint32_t off = (uint32_t)(mr * 128 + c * 2);
        off = off ^ ((off >> 3) & 0x70);
        *(uint2*)(db + base + off) = pk;
    }
}

// ---------------- fp16 mma.sync GEMM (128x128, CTA swizzle) ------------------
#define G_STG    4
#define G_TB     16384
#define G_SMEM   (1024 + G_STG*2*G_TB)         // 132096
#define GROUP_M  8

__global__ __launch_bounds__(288, 1) void gemm_mma(
    const __half* __restrict__ A2, const __half* __restrict__ B2,
    const float* __restrict__ bias, const float* __restrict__ E,
    float* __restrict__ C, int N, int K2, int mode)
{
    extern __shared__ char sm[];
    const uint32_t sb = smem_u32(sm);
    const int tid = threadIdx.x, wid = tid >> 5, lane = tid & 31;

    const uint32_t MFULL  = sb;
    const uint32_t MEMPTY = sb + 256;
    const uint32_t SA     = sb + 1024;
    const uint32_t SBq    = SA + G_STG * G_TB;

    if (tid == 0) {
        #pragma unroll
        for (int s = 0; s < G_STG; s++) { MBAR_INIT(MFULL + s*8, 1); MBAR_INIT(MEMPTY + s*8, 8); }
    }
    __syncthreads();

    const int ktiles = K2 >> 6;
    const int gridN = gridDim.x;
    const int bid   = blockIdx.y * gridN + blockIdx.x;
    const int tpg   = GROUP_M * gridN;
    const int grp   = bid / tpg, rem = bid - grp * tpg;
    const int mt    = grp * GROUP_M + (rem % GROUP_M);
    const int nt    = rem / GROUP_M;

    float d[2][8][4];
    #pragma unroll
    for (int a = 0; a < 2; a++)
        #pragma unroll
        for (int b = 0; b < 8; b++)
            #pragma unroll
            for (int c = 0; c < 4; c++) d[a][b][c] = 0.f;

    if (wid == 8) {
        if (elect_one()) {
            const char* Ag = (const char*)A2 + (size_t)mt * ktiles * G_TB;
            const char* Bg = (const char*)B2 + (size_t)nt * ktiles * G_TB;
            int s = 0, ph = 1;
            for (int kt = 0; kt < ktiles; kt++) {
                MBAR_WAIT(MEMPTY + s*8, ph);
                MBAR_EXPECT(MFULL + s*8, 2*G_TB);
                BULK_G2S(SA  + s*G_TB, Ag + (size_t)kt*G_TB, G_TB, MFULL + s*8);
                BULK_G2S(SBq + s*G_TB, Bg + (size_t)kt*G_TB, G_TB, MFULL + s*8);
                if (++s == G_STG) { s = 0; ph ^= 1; }
            }
        }
    } else {
        const int wm = (wid & 3) * 32;
        const int wn = (wid >> 2) * 64;
        const uint32_t rsub   = (uint32_t)(((lane >> 3) & 1) * 8 + (lane & 7));
        const uint32_t ksel   = (uint32_t)((lane >> 4) * 16);
        const uint32_t cmask  = (uint32_t)((lane & 7) << 4);
        const uint32_t aRowOff = (uint32_t)(wm + rsub) * 128;
        const uint32_t bRowOff = (uint32_t)(wn + rsub) * 128;

        int s = 0, ph = 0;
        for (int kt = 0; kt < ktiles; kt++) {
            MBAR_WAIT(MFULL + s*8, ph);
            const uint32_t sa  = SA  + s*G_TB;
            const uint32_t sbb = SBq + s*G_TB;
            #pragma unroll
            for (int kk4 = 0; kk4 < 4; kk4++) {
                const uint32_t ko = (uint32_t)(kk4*32 + ksel) ^ cmask;
                uint32_t af[2][4];
                #pragma unroll
                for (int mi = 0; mi < 2; mi++)
                    LDSM_X4(af[mi][0], af[mi][1], af[mi][2], af[mi][3],
                            sa + aRowOff + mi*2048 + ko);
                uint32_t bf[8][2];
                #pragma unroll
                for (int ng = 0; ng < 4; ng++) {
                    uint32_t t0, t1, t2, t3;
                    LDSM_X4(t0, t1, t2, t3, sbb + bRowOff + ng*2048 + ko);
                    bf[2*ng][0] = t0; bf[2*ng+1][0] = t1;
                    bf[2*ng][1] = t2; bf[2*ng+1][1] = t3;
                }
                #pragma unroll
                for (int mi = 0; mi < 2; mi++)
                    #pragma unroll
                    for (int ni = 0; ni < 8; ni++)
                        MMA16816H(d[mi][ni], af[mi], bf[ni]);
            }
            if (lane == 0) MBAR_ARRIVE(MEMPTY + s*8);
            if (++s == G_STG) { s = 0; ph ^= 1; }
        }
    }

    __syncthreads();

    float* st = (float*)(sm + 1024);
    if (wid < 8) {
        const int wm = (wid & 3) * 32;
        const int wn = (wid >> 2) * 64;
        const int r0 = lane >> 2;
        const int cc = (lane & 3) * 2;
        #pragma unroll
        for (int mi = 0; mi < 2; mi++)
            #pragma unroll
            for (int ni = 0; ni < 8; ni++) {
                const int r = wm + mi*16 + r0;
                const int c = wn + ni*8 + cc;
                st[r*132 + c]       = d[mi][ni][0];
                st[r*132 + c + 1]   = d[mi][ni][1];
                st[(r+8)*132 + c]   = d[mi][ni][2];
                st[(r+8)*132 + c+1] = d[mi][ni][3];
            }
    }
    __syncthreads();

    if (tid < 256) {
        const int r0 = tid >> 5;
        const int c  = (tid & 31) * 4;
        const int n  = nt*128 + c;
        float4 bv = make_float4(0.f, 0.f, 0.f, 0.f);
        if (bias) bv = *(const float4*)(bias + n);
        #pragma unroll 4
        for (int rp = 0; rp < 16; rp++) {
            const int r = rp*8 + r0;
            const size_t idx = (size_t)(mt*128 + r) * N + n;
            float4 v = *(float4*)&st[r*132 + c];
            v.x += bv.x; v.y += bv.y; v.z += bv.z; v.w += bv.w;
            if (mode == 1) {
                float4 e = *(const float4*)(E + idx);
                v.x = e.x + fmaxf(v.x, 0.f); v.y = e.y + fmaxf(v.y, 0.f);
                v.z = e.z + fmaxf(v.z, 0.f); v.w = e.w + fmaxf(v.w, 0.f);
            } else if (mode == 2) {
                float4 e = *(const float4*)(E + idx);
                v.x += e.x; v.y += e.y; v.z += e.z; v.w += e.w;
            }
            *(float4*)(C + idx) = v;
        }
    }
}

// ---------------- tf32 tensor-core causal flash attention --------------------
#define AT_SMEMF (3*64*132 + 64*68 + 128)
__global__ __launch_bounds__(256) void attn_tc(
    const float* __restrict__ qkv, float* __restrict__ out)
{
    extern __shared__ float s[];
    float* Qs = s;                 // 64 x 132 (tf32 vals, pre-scaled)
    float* Ks = Qs + 64*132;
    float* Vs = Ks + 64*132;
    float* Sb = Vs + 64*132;       // 64 x 68
    float* Cr = Sb + 64*68;        // 64 corr
    float* Ll = Cr + 64;           // 64 l

    const int tid = threadIdx.x, wid = tid >> 5, lane = tid & 31;
    const int qt = blockIdx.x, hh = blockIdx.y, bb = blockIdx.z;
    const int q0 = qt * 64;

    #pragma unroll
    for (int i = 0; i < 8; i++) {
        int id = i*256 + tid;
        int rr = id >> 5, c4 = (id & 31) * 4;
        float4 v = *(const float4*)(qkv + (size_t)(bb*SS + q0 + rr) * QKVW + hh*HD + c4);
        Qs[rr*132 + c4 + 0] = to_tf32(v.x * 0.08838834764831845f);
        Qs[rr*132 + c4 + 1] = to_tf32(v.y * 0.08838834764831845f);
        Qs[rr*132 + c4 + 2] = to_tf32(v.z * 0.08838834764831845f);
        Qs[rr*132 + c4 + 3] = to_tf32(v.w * 0.08838834764831845f);
    }

    const int srow = tid >> 2;
    const int sg   = tid & 3;
    float mrun = -INFINITY, lrun = 0.f;

    float o[8][4];
    #pragma unroll
    for (int i = 0; i < 8; i++)
        #pragma unroll
        for (int j = 0; j < 4; j++) o[i][j] = 0.f;

    const int wm  = (wid & 3) * 16;
    const int wnk = (wid >> 2) * 32;
    const int wnv = (wid >> 2) * 64;
    const int rA0 = wm + lane/4, rA1 = rA0 + 8;

    const int njt = qt + 1;
    for (int jt = 0; jt < njt; jt++) {
        const int j0 = jt * 64;
        __syncthreads();
        #pragma unroll
        for (int i = 0; i < 8; i++) {
            int id = i*256 + tid;
            int rr = id >> 5, c4 = (id & 31) * 4;
            size_t base = (size_t)(bb*SS + j0 + rr) * QKVW + hh*HD + c4;
            float4 kv = *(const float4*)(qkv + base + HH*HD);
            float4 vv = *(const float4*)(qkv + base + 2*HH*HD);
            Ks[rr*132 + c4 + 0] = to_tf32(kv.x); Ks[rr*132 + c4 + 1] = to_tf32(kv.y);
            Ks[rr*132 + c4 + 2] = to_tf32(kv.z); Ks[rr*132 + c4 + 3] = to_tf32(kv.w);
            Vs[rr*132 + c4 + 0] = to_tf32(vv.x); Vs[rr*132 + c4 + 1] = to_tf32(vv.y);
            Vs[rr*132 + c4 + 2] = to_tf32(vv.z); Vs[rr*132 + c4 + 3] = to_tf32(vv.w);
        }
        __syncthreads();

        {
            float c[4][4];
            #pragma unroll
            for (int i = 0; i < 4; i++)
                #pragma unroll
                for (int j = 0; j < 4; j++) c[i][j] = 0.f;
            #pragma unroll
            for (int ks = 0; ks < 16; ks++) {
                const int k0 = ks*8 + (lane & 3);
                uint32_t a0 = __float_as_uint(Qs[rA0*132 + k0]);
                uint32_t a1 = __float_as_uint(Qs[rA1*132 + k0]);
                uint32_t a2 = __float_as_uint(Qs[rA0*132 + k0 + 4]);
                uint32_t a3 = __float_as_uint(Qs[rA1*132 + k0 + 4]);
                #pragma unroll
                for (int ntl = 0; ntl < 4; ntl++) {
                    const int nrow = wnk + ntl*8 + lane/4;
                    uint32_t b0 = __float_as_uint(Ks[nrow*132 + k0]);
                    uint32_t b1 = __float_as_uint(Ks[nrow*132 + k0 + 4]);
                    MMA1688TF(c[ntl], a0, a1, a2, a3, b0, b1);
                }
            }
            const int cc = (lane & 3) * 2;
            #pragma unroll
            for (int ntl = 0; ntl < 4; ntl++) {
                const int cb = wnk + ntl*8 + cc;
                Sb[rA0*68 + cb]     = c[ntl][0];
                Sb[rA0*68 + cb + 1] = c[ntl][1];
                Sb[rA1*68 + cb]     = c[ntl][2];
                Sb[rA1*68 + cb + 1] = c[ntl][3];
            }
        }
        __syncthreads();

        {
            const bool diag = (jt == qt);
            const int qi_rel = srow;
            float mx = -INFINITY;
            float pv[16];
            #pragma unroll
            for (int j = 0; j < 16; j++) {
                const int c = sg + 4*j;
                float v = Sb[srow*68 + c];
                if (diag && c > qi_rel) v = -INFINITY;
                pv[j] = v;
                mx = fmaxf(mx, v);
            }
            mx = fmaxf(mx, __shfl_xor_sync(0xffffffffu, mx, 1));
            mx = fmaxf(mx, __shfl_xor_sync(0xffffffffu, mx, 2));
            const float mNew = fmaxf(mrun, mx);
            const float corr = __expf(mrun - mNew);
            float ls = 0.f;
            #pragma unroll
            for (int j = 0; j < 16; j++) {
                const int c = sg + 4*j;
                float p = (pv[j] == -INFINITY) ? 0.f : to_tf32(__expf(pv[j] - mNew));
                Sb[srow*68 + c] = p;
                ls += p;
            }
            ls += __shfl_xor_sync(0xffffffffu, ls, 1);
            ls += __shfl_xor_sync(0xffffffffu, ls, 2);
            lrun = lrun * corr + ls;
            mrun = mNew;
            if (sg == 0) { Cr[srow] = corr; Ll[srow] = lrun; }
        }
        __syncthreads();

        {
            const float c0 = Cr[rA0], c1 = Cr[rA1];
            #pragma unroll
            for (int i = 0; i < 8; i++) {
                o[i][0] *= c0; o[i][1] *= c0;
                o[i][2] *= c1; o[i][3] *= c1;
            }
            #pragma unroll
            for (int ks = 0; ks < 8; ks++) {
                const int k0 = ks*8 + (lane & 3);
                uint32_t a0 = __float_as_uint(Sb[rA0*68 + k0]);
                uint32_t a1 = __float_as_uint(Sb[rA1*68 + k0]);
                uint32_t a2 = __float_as_uint(Sb[rA0*68 + k0 + 4]);
                uint32_t a3 = __float_as_uint(Sb[rA1*68 + k0 + 4]);
                #pragma unroll
                for (int ntl = 0; ntl < 8; ntl++) {
                    const int ncol = wnv + ntl*8 + lane/4;
                    uint32_t b0 = __float_as_uint(Vs[k0*132 + ncol]);
                    uint32_t b1 = __float_as_uint(Vs[(k0+4)*132 + ncol]);
                    MMA1688TF(o[ntl], a0, a1, a2, a3, b0, b1);
                }
            }
        }
    }
    __syncthreads();

    {
        const float inv0 = 1.f / Ll[rA0];
        const float inv1 = 1.f / Ll[rA1];
        const size_t ob0 = (size_t)((bb*HH + hh)*SS + q0 + rA0) * HD;
        const size_t ob1 = (size_t)((bb*HH + hh)*SS + q0 + rA1) * HD;
        const int cc = (lane & 3) * 2;
        #pragma unroll
        for (int ntl = 0; ntl < 8; ntl++) {
            const int cb = wnv + ntl*8 + cc;
            *(float2*)(out + ob0 + cb) = make_float2(o[ntl][0]*inv0, o[ntl][1]*inv0);
            *(float2*)(out + ob1 + cb) = make_float2(o[ntl][2]*inv1, o[ntl][3]*inv1);
        }
    }
}

// ---------------- launch ------------------------------------------------------
static inline void conv(const float* s, __half* d, int rows, int K, int isw) {
    int total4 = rows * (K >> 2);
    convert2<<<(total4 + 255) / 256, 256>>>(s, d, K, isw, total4);
}

extern "C" void kernel_launch(void* const* d_in, const int* in_sizes, int n_in,
                              void* d_out, int out_size)
{
    (void)in_sizes; (void)n_in; (void)out_size;
    const float* x     = (const float*)d_in[0];
    const float* rms_w = (const float*)d_in[1];
    const float* w_qkv = (const float*)d_in[2];
    const float* w_out = (const float*)d_in[3];
    const float* w1    = (const float*)d_in[4];
    const float* b1    = (const float*)d_in[5];
    const float* w3    = (const float*)d_in[6];
    const float* b3    = (const float*)d_in[7];
    const float* w2    = (const float*)d_in[8];
    const float* b2    = (const float*)d_in[9];
    float* out = (float*)d_out;

    float *xn,*qkv,*att,*h,*a1,*gg;
    cudaGetSymbolAddress((void**)&xn,  g_xn);
    cudaGetSymbolAddress((void**)&qkv, g_qkv);
    cudaGetSymbolAddress((void**)&att, g_att);
    cudaGetSymbolAddress((void**)&h,   g_h);
    cudaGetSymbolAddress((void**)&a1,  g_a1);
    cudaGetSymbolAddress((void**)&gg,  g_g);
    __half *xn2,*att2,*h2,*gg2,*wqkv2,*wout2,*w12,*w32,*w22;
    cudaGetSymbolAddress((void**)&xn2,   g_xn2);
    cudaGetSymbolAddress((void**)&att2,  g_att2);
    cudaGetSymbolAddress((void**)&h2,    g_h2);
    cudaGetSymbolAddress((void**)&gg2,   g_gg2);
    cudaGetSymbolAddress((void**)&wqkv2, g_wqkv2);
    cudaGetSymbolAddress((void**)&wout2, g_wout2);
    cudaGetSymbolAddress((void**)&w12,   g_w12);
    cudaGetSymbolAddress((void**)&w32,   g_w32);
    cudaGetSymbolAddress((void**)&w22,   g_w22);

    cudaFuncSetAttribute(gemm_mma, cudaFuncAttributeMaxDynamicSharedMemorySize, G_SMEM);
    const int attn_smem = AT_SMEMF * (int)sizeof(float);
    cudaFuncSetAttribute(attn_tc, cudaFuncAttributeMaxDynamicSharedMemorySize, attn_smem);

    // weight conversions
    conv(w_qkv, wqkv2, QKVW, DD, 1);
    conv(w_out, wout2, DD,   DD, 1);
    conv(w1,    w12,   FF,   DD, 1);
    conv(w3,    w32,   FF,   DD, 1);
    conv(w2,    w22,   DD,   FF, 1);

    // 1) RMSNorm + convert
    rmsnorm_kernel<<<MM, 256>>>(x, rms_w, xn);
    conv(xn, xn2, MM, DD, 0);

    // 2) QKV projection
    gemm_mma<<<dim3(QKVW/128, MM/128), 288, G_SMEM>>>(xn2, wqkv2, nullptr, nullptr, qkv, QKVW, 2*DD, 0);

    // 3) attention (tf32 tensor cores)
    attn_tc<<<dim3(SS/64, HH, BB), 256, attn_smem>>>(qkv, att);
    conv(att, att2, MM, DD, 0);

    // 4) out projection
    gemm_mma<<<dim3(DD/128, MM/128), 288, G_SMEM>>>(att2, wout2, nullptr, nullptr, h, DD, 2*DD, 0);
    conv(h, h2, MM, DD, 0);

    // 5) a1 = h @ w1^T + b1
    gemm_mma<<<dim3(FF/128, MM/128), 288, G_SMEM>>>(h2, w12, b1, nullptr, a1, FF, 2*DD, 0);

    // 6) g = a1 + relu(h @ w3^T + b3)
    gemm_mma<<<dim3(FF/128, MM/128), 288, G_SMEM>>>(h2, w32, b3, a1, gg, FF, 2*DD, 1);
    conv(gg, gg2, MM, FF, 0);

    // 7) out = x + g @ w2^T + b2
    gemm_mma<<<dim3(DD/128, MM/128), 288, G_SMEM>>>(gg2, w22, b2, x, out, DD, 2*FF, 2);
}